// round 1
// baseline (speedup 1.0000x reference)
#include <cuda_runtime.h>
#include <cstdint>

// Problem constants (fixed by the dataset)
#define N_ATOMS  8000
#define N_PAIRS  80000
#define NF_IN    32
#define NF_OUT   32
#define N_DIST   16
#define N_COMP   4
#define N_INV    2
#define HARD_CUTOFF 6.5f
#define GN_EPS   1e-5f

// Scratch (static device arrays — no allocation)
__device__ float g_proj[N_ATOMS * N_DIST * NF_OUT];   // (j, d, o) : 16.4 MB
__device__ float g_sense[N_PAIRS * N_DIST];           // (p, d)    : 5.1 MB

// ---------------------------------------------------------------------------
// K1: g[j,d,o] = sum_f feat[j,f] * W[d,o,f]
// thread per (j,d,o); lanes within a warp share (j,d), vary o.
// ---------------------------------------------------------------------------
__global__ void __launch_bounds__(256) proj_kernel(
    const float* __restrict__ feat, const float* __restrict__ W)
{
    int idx = blockIdx.x * blockDim.x + threadIdx.x;
    if (idx >= N_ATOMS * N_DIST * NF_OUT) return;
    int j = idx >> 9;           // / 512
    int r = idx & 511;
    int d = r >> 5;
    int o = r & 31;
    const float4* fr = (const float4*)(feat + (size_t)j * NF_IN);
    const float4* wr = (const float4*)(W + ((size_t)d * NF_OUT + o) * NF_IN);
    float s = 0.f;
#pragma unroll
    for (int k = 0; k < NF_IN / 4; ++k) {
        float4 a = fr[k];
        float4 b = wr[k];
        s = fmaf(a.x, b.x, s);
        s = fmaf(a.y, b.y, s);
        s = fmaf(a.z, b.z, s);
        s = fmaf(a.w, b.w, s);
    }
    g_proj[idx] = s;
}

// ---------------------------------------------------------------------------
// K2: sense[p,d] = exp(-0.5*((1/dist - mu_d)/sigma_d)^2) * cos^2 cutoff
// ---------------------------------------------------------------------------
__global__ void __launch_bounds__(256) sense_kernel(
    const float* __restrict__ dist,
    const float* __restrict__ mu,
    const float* __restrict__ sigma)
{
    int idx = blockIdx.x * blockDim.x + threadIdx.x;
    if (idx >= N_PAIRS * N_DIST) return;
    int p = idx >> 4;
    int d = idx & 15;
    float dd   = dist[p];
    float invd = 1.0f / dd;
    float t    = (invd - mu[d]) / sigma[d];
    float base = expf(-0.5f * t * t);
    float cut  = 0.f;
    if (dd < HARD_CUTOFF) {
        float c = cosf(0.5f * 3.14159265358979323846f * dd / HARD_CUTOFF);
        cut = c * c;
    }
    g_sense[idx] = base * cut;
}

// ---------------------------------------------------------------------------
// K3 (main): one warp per atom (lane = output channel o).
//   tf[c,o] += rhat[p,c] * sum_d sense[p,d] * g[j,d,o]     over this atom's pairs
//   invariants -> GroupNorm (warp shuffles) -> mixing matmul -> + self part
// ---------------------------------------------------------------------------
#define WPB 8  // warps per block

__device__ __forceinline__ float warp_sum(float v) {
#pragma unroll
    for (int s = 16; s; s >>= 1) v += __shfl_xor_sync(0xffffffffu, v, s);
    return v;
}

__global__ void __launch_bounds__(WPB * 32) main_kernel(
    const float* __restrict__ rhat,         // (P, 4)
    const int*   __restrict__ pair_first,   // (P,) sorted
    const int*   __restrict__ pair_second,  // (P,)
    const float* __restrict__ in_feat,      // (N, 32)
    const float* __restrict__ selfw,        // (32, 32) [o, f]
    const float* __restrict__ selfb,        // (32,)
    const float* __restrict__ mixw,         // (32, 2, 32) flat 2048
    const float* __restrict__ gnw,          // (64,)
    const float* __restrict__ gnb,          // (64,)
    float*       __restrict__ out)          // (N, 32)
{
    __shared__ float smMix[2048];           // [ (o_in*2+g)*32 + o_out ]
    __shared__ float smSelfT[1024];         // transposed: [f*32 + o]
    __shared__ float smB[32], smGnW[64], smGnB[64];
    __shared__ float smXn[WPB][64];

    int tid = threadIdx.x;
    for (int i = tid; i < 2048; i += blockDim.x) smMix[i] = mixw[i];
    for (int i = tid; i < 1024; i += blockDim.x) {
        int o = i >> 5, f = i & 31;
        smSelfT[f * 32 + o] = selfw[i];
    }
    if (tid < 32) smB[tid] = selfb[tid];
    if (tid < 64) { smGnW[tid] = gnw[tid]; smGnB[tid] = gnb[tid]; }
    __syncthreads();

    int warp = tid >> 5, lane = tid & 31;
    int a = blockIdx.x * WPB + warp;
    if (a >= N_ATOMS) return;

    // segment [lo, hi) of this atom's pairs via binary search (lane 0)
    int lo = 0, hi = 0;
    if (lane == 0) {
        int l = 0, r = N_PAIRS;
        while (l < r) { int m = (l + r) >> 1; if (pair_first[m] < a) l = m + 1; else r = m; }
        lo = l;
        r = N_PAIRS;
        while (l < r) { int m = (l + r) >> 1; if (pair_first[m] < a + 1) l = m + 1; else r = m; }
        hi = l;
    }
    lo = __shfl_sync(0xffffffffu, lo, 0);
    hi = __shfl_sync(0xffffffffu, hi, 0);

    float acc0 = 0.f, acc1 = 0.f, acc2 = 0.f, acc3 = 0.f;
    for (int p = lo; p < hi; ++p) {
        int j = pair_second[p];                       // broadcast load
        const float* gp = g_proj + (size_t)j * (N_DIST * NF_OUT) + lane;
        const float* sp = g_sense + (size_t)p * N_DIST;
        float h = 0.f;
#pragma unroll
        for (int d = 0; d < N_DIST; ++d)
            h = fmaf(sp[d], gp[d * 32], h);           // sp[d] broadcast across warp
        float4 r = *(const float4*)(rhat + (size_t)p * 4);
        acc0 = fmaf(r.x, h, acc0);
        acc1 = fmaf(r.y, h, acc1);
        acc2 = fmaf(r.z, h, acc2);
        acc3 = fmaf(r.w, h, acc3);
    }

    // invariants: l=0 scalar, |l=1|^2
    float inv0 = acc0;
    float inv1 = acc1 * acc1 + acc2 * acc2 + acc3 * acc3;

    // GroupNorm per group (channel dim = 32 lanes), biased var
    float m0 = warp_sum(inv0) * (1.f / 32.f);
    float q0 = warp_sum(inv0 * inv0) * (1.f / 32.f);
    float xn0 = (inv0 - m0) * rsqrtf(q0 - m0 * m0 + GN_EPS) * smGnW[lane] + smGnB[lane];
    float m1 = warp_sum(inv1) * (1.f / 32.f);
    float q1 = warp_sum(inv1 * inv1) * (1.f / 32.f);
    float xn1 = (inv1 - m1) * rsqrtf(q1 - m1 * m1 + GN_EPS) * smGnW[32 + lane] + smGnB[32 + lane];

    // stage normalized invariants: norm_inv layout index o*2+g
    smXn[warp][lane * 2 + 0] = xn0;
    smXn[warp][lane * 2 + 1] = xn1;
    __syncwarp();

    // mixing: out_o = sum_k smXn[k] * mixw[k*32 + o],  k = o_in*2+g
    float mix = 0.f;
#pragma unroll
    for (int k = 0; k < 64; ++k)
        mix = fmaf(smXn[warp][k], smMix[k * 32 + lane], mix);

    // self interaction: out_o += b[o] + sum_f x[f] * selfw[o,f]
    float x = in_feat[(size_t)a * 32 + lane];
    float sp_acc = smB[lane];
#pragma unroll
    for (int f = 0; f < 32; ++f) {
        float xf = __shfl_sync(0xffffffffu, x, f);
        sp_acc = fmaf(xf, smSelfT[f * 32 + lane], sp_acc);
    }

    out[(size_t)a * 32 + lane] = mix + sp_acc;
}

// ---------------------------------------------------------------------------
extern "C" void kernel_launch(void* const* d_in, const int* in_sizes, int n_in,
                              void* d_out, int out_size)
{
    const float* in_feat = (const float*)d_in[0];
    const float* rhat    = (const float*)d_in[1];
    const float* dist    = (const float*)d_in[2];
    const float* intw    = (const float*)d_in[3];
    const float* selfw   = (const float*)d_in[4];
    const float* selfb   = (const float*)d_in[5];
    const float* mixw    = (const float*)d_in[6];
    const float* gnw     = (const float*)d_in[7];
    const float* gnb     = (const float*)d_in[8];
    const float* mu      = (const float*)d_in[9];
    const float* sigma   = (const float*)d_in[10];
    const int*   pf      = (const int*)d_in[11];
    const int*   ps      = (const int*)d_in[12];
    float* out = (float*)d_out;

    {
        int total = N_ATOMS * N_DIST * NF_OUT;
        proj_kernel<<<(total + 255) / 256, 256>>>(in_feat, intw);
    }
    {
        int total = N_PAIRS * N_DIST;
        sense_kernel<<<(total + 255) / 256, 256>>>(dist, mu, sigma);
    }
    {
        int blocks = (N_ATOMS + WPB - 1) / WPB;
        main_kernel<<<blocks, WPB * 32>>>(rhat, pf, ps, in_feat,
                                          selfw, selfb, mixw, gnw, gnb, out);
    }
}

// round 5
// speedup vs baseline: 2.1302x; 2.1302x over previous
#include <cuda_runtime.h>
#include <cstdint>

// Problem constants (fixed by the dataset)
#define N_ATOMS  8000
#define N_PAIRS  80000
#define NF_IN    32
#define NF_OUT   32
#define N_DIST   16
#define N_COMP   4
#define N_INV    2
#define HARD_CUTOFF 6.5f
#define GN_EPS   1e-5f

// Scratch (static device arrays — no allocation)
// g_proj layout: (j, o, d)  -> g_proj[j*512 + o*16 + d]
__device__ float g_proj[N_ATOMS * N_DIST * NF_OUT];   // 16.4 MB
__device__ float g_sense[N_PAIRS * N_DIST];           // (p, d) : 5.1 MB

// ---------------------------------------------------------------------------
// K1: g[j,o,d] = sum_f feat[j,f] * W[d,o,f]
// Warp handles 4 atoms; lane = o; 16 d-accumulators per atom.
// W staged in smem in two 32KB half-tiles: smW[fh*512 + d*32 + o].
// ---------------------------------------------------------------------------
#define PROJ_THREADS 256   // 8 warps -> 32 atoms/block -> 250 blocks

__global__ void __launch_bounds__(PROJ_THREADS) proj_kernel(
    const float* __restrict__ feat, const float* __restrict__ W)
{
    __shared__ float smW[16 * 512];   // 32 KB: [fh][d*32+o]
    int tid  = threadIdx.x;
    int warp = tid >> 5, lane = tid & 31;
    int atom0 = blockIdx.x * 32 + warp * 4;

    // lane holds feat[j][lane] for each of its 4 atoms
    float x0 = feat[(size_t)(atom0 + 0) * 32 + lane];
    float x1 = feat[(size_t)(atom0 + 1) * 32 + lane];
    float x2 = feat[(size_t)(atom0 + 2) * 32 + lane];
    float x3 = feat[(size_t)(atom0 + 3) * 32 + lane];

    float acc0[16], acc1[16], acc2[16], acc3[16];
#pragma unroll
    for (int d = 0; d < 16; ++d) { acc0[d] = acc1[d] = acc2[d] = acc3[d] = 0.f; }

    for (int half = 0; half < 2; ++half) {
        __syncthreads();
        // Load W half-tile: smW[fh*512 + s] = W[s*32 + half*16 + fh], s = d*32+o
        for (int i = tid; i < 2048; i += PROJ_THREADS) {
            int s   = i >> 2;
            int fh4 = (i & 3) * 4;
            float4 w = *(const float4*)(W + (size_t)s * 32 + half * 16 + fh4);
            smW[(fh4 + 0) * 512 + s] = w.x;
            smW[(fh4 + 1) * 512 + s] = w.y;
            smW[(fh4 + 2) * 512 + s] = w.z;
            smW[(fh4 + 3) * 512 + s] = w.w;
        }
        __syncthreads();
#pragma unroll
        for (int fh = 0; fh < 16; ++fh) {
            int f = half * 16 + fh;
            float xf0 = __shfl_sync(0xffffffffu, x0, f);
            float xf1 = __shfl_sync(0xffffffffu, x1, f);
            float xf2 = __shfl_sync(0xffffffffu, x2, f);
            float xf3 = __shfl_sync(0xffffffffu, x3, f);
            const float* wrow = smW + fh * 512 + lane;
#pragma unroll
            for (int d = 0; d < 16; ++d) {
                float w = wrow[d * 32];          // conflict-free LDS
                acc0[d] = fmaf(xf0, w, acc0[d]);
                acc1[d] = fmaf(xf1, w, acc1[d]);
                acc2[d] = fmaf(xf2, w, acc2[d]);
                acc3[d] = fmaf(xf3, w, acc3[d]);
            }
        }
    }

    // Store g[j][o][d]: per-lane 16 consecutive floats -> 4x STG.128
    float4* o0 = (float4*)(g_proj + (size_t)(atom0 + 0) * 512 + lane * 16);
    float4* o1 = (float4*)(g_proj + (size_t)(atom0 + 1) * 512 + lane * 16);
    float4* o2 = (float4*)(g_proj + (size_t)(atom0 + 2) * 512 + lane * 16);
    float4* o3 = (float4*)(g_proj + (size_t)(atom0 + 3) * 512 + lane * 16);
#pragma unroll
    for (int q = 0; q < 4; ++q) {
        o0[q] = make_float4(acc0[q*4], acc0[q*4+1], acc0[q*4+2], acc0[q*4+3]);
        o1[q] = make_float4(acc1[q*4], acc1[q*4+1], acc1[q*4+2], acc1[q*4+3]);
        o2[q] = make_float4(acc2[q*4], acc2[q*4+1], acc2[q*4+2], acc2[q*4+3]);
        o3[q] = make_float4(acc3[q*4], acc3[q*4+1], acc3[q*4+2], acc3[q*4+3]);
    }
}

// ---------------------------------------------------------------------------
// K2: sense[p,d] = exp(-0.5*((1/dist - mu_d)/sigma_d)^2) * cos^2 cutoff
// ---------------------------------------------------------------------------
__global__ void __launch_bounds__(256) sense_kernel(
    const float* __restrict__ dist,
    const float* __restrict__ mu,
    const float* __restrict__ sigma)
{
    int idx = blockIdx.x * blockDim.x + threadIdx.x;
    if (idx >= N_PAIRS * N_DIST) return;
    int p = idx >> 4;
    int d = idx & 15;
    float dd   = dist[p];
    float invd = 1.0f / dd;
    float t    = (invd - mu[d]) / sigma[d];
    float base = expf(-0.5f * t * t);
    float cut  = 0.f;
    if (dd < HARD_CUTOFF) {
        float c = cosf(0.5f * 3.14159265358979323846f * dd / HARD_CUTOFF);
        cut = c * c;
    }
    g_sense[idx] = base * cut;
}

// ---------------------------------------------------------------------------
// K3 (main): one warp per atom (lane = output channel o).
// ---------------------------------------------------------------------------
#define WPB 8  // warps per block

__device__ __forceinline__ float warp_sum(float v) {
#pragma unroll
    for (int s = 16; s; s >>= 1) v += __shfl_xor_sync(0xffffffffu, v, s);
    return v;
}

__global__ void __launch_bounds__(WPB * 32) main_kernel(
    const float* __restrict__ rhat,         // (P, 4)
    const int*   __restrict__ pair_first,   // (P,) sorted
    const int*   __restrict__ pair_second,  // (P,)
    const float* __restrict__ in_feat,      // (N, 32)
    const float* __restrict__ selfw,        // (32, 32) [o, f]
    const float* __restrict__ selfb,        // (32,)
    const float* __restrict__ mixw,         // (32, 2, 32) flat 2048
    const float* __restrict__ gnw,          // (64,)
    const float* __restrict__ gnb,          // (64,)
    float*       __restrict__ out)          // (N, 32)
{
    __shared__ float smMix[2048];           // [ (o_in*2+g)*32 + o_out ]
    __shared__ float smSelfT[1024];         // transposed: [f*32 + o]
    __shared__ float smB[32], smGnW[64], smGnB[64];
    __shared__ float smXn[WPB][64];

    int tid = threadIdx.x;
    for (int i = tid; i < 2048; i += blockDim.x) smMix[i] = mixw[i];
    for (int i = tid; i < 1024; i += blockDim.x) {
        int o = i >> 5, f = i & 31;
        smSelfT[f * 32 + o] = selfw[i];
    }
    if (tid < 32) smB[tid] = selfb[tid];
    if (tid < 64) { smGnW[tid] = gnw[tid]; smGnB[tid] = gnb[tid]; }
    __syncthreads();

    int warp = tid >> 5, lane = tid & 31;
    int a = blockIdx.x * WPB + warp;
    if (a >= N_ATOMS) return;

    // segment [lo, hi) of this atom's pairs via binary search (lane 0)
    int lo = 0, hi = 0;
    if (lane == 0) {
        int l = 0, r = N_PAIRS;
        while (l < r) { int m = (l + r) >> 1; if (pair_first[m] < a) l = m + 1; else r = m; }
        lo = l;
        r = N_PAIRS;
        while (l < r) { int m = (l + r) >> 1; if (pair_first[m] < a + 1) l = m + 1; else r = m; }
        hi = l;
    }
    lo = __shfl_sync(0xffffffffu, lo, 0);
    hi = __shfl_sync(0xffffffffu, hi, 0);

    float acc0 = 0.f, acc1 = 0.f, acc2 = 0.f, acc3 = 0.f;
    for (int p = lo; p < hi; ++p) {
        int j = pair_second[p];                       // broadcast load
        const float4* gp = (const float4*)(g_proj + (size_t)j * 512 + lane * 16);
        float4 g0 = gp[0], g1 = gp[1], g2 = gp[2], g3 = gp[3];
        const float4* sp = (const float4*)(g_sense + (size_t)p * 16);
        float4 s0 = sp[0], s1 = sp[1], s2 = sp[2], s3 = sp[3];
        float h;
        h  = g0.x * s0.x; h = fmaf(g0.y, s0.y, h);
        h  = fmaf(g0.z, s0.z, h); h = fmaf(g0.w, s0.w, h);
        h  = fmaf(g1.x, s1.x, h); h = fmaf(g1.y, s1.y, h);
        h  = fmaf(g1.z, s1.z, h); h = fmaf(g1.w, s1.w, h);
        h  = fmaf(g2.x, s2.x, h); h = fmaf(g2.y, s2.y, h);
        h  = fmaf(g2.z, s2.z, h); h = fmaf(g2.w, s2.w, h);
        h  = fmaf(g3.x, s3.x, h); h = fmaf(g3.y, s3.y, h);
        h  = fmaf(g3.z, s3.z, h); h = fmaf(g3.w, s3.w, h);
        float4 r = *(const float4*)(rhat + (size_t)p * 4);   // broadcast
        acc0 = fmaf(r.x, h, acc0);
        acc1 = fmaf(r.y, h, acc1);
        acc2 = fmaf(r.z, h, acc2);
        acc3 = fmaf(r.w, h, acc3);
    }

    // invariants: l=0 scalar, |l=1|^2
    float inv0 = acc0;
    float inv1 = acc1 * acc1 + acc2 * acc2 + acc3 * acc3;

    // GroupNorm per group (channel dim = 32 lanes), biased var
    float m0 = warp_sum(inv0) * (1.f / 32.f);
    float q0 = warp_sum(inv0 * inv0) * (1.f / 32.f);
    float xn0 = (inv0 - m0) * rsqrtf(q0 - m0 * m0 + GN_EPS) * smGnW[lane] + smGnB[lane];
    float m1 = warp_sum(inv1) * (1.f / 32.f);
    float q1 = warp_sum(inv1 * inv1) * (1.f / 32.f);
    float xn1 = (inv1 - m1) * rsqrtf(q1 - m1 * m1 + GN_EPS) * smGnW[32 + lane] + smGnB[32 + lane];

    // stage normalized invariants: norm_inv layout index o*2+g
    smXn[warp][lane * 2 + 0] = xn0;
    smXn[warp][lane * 2 + 1] = xn1;
    __syncwarp();

    // mixing: out_o = sum_k smXn[k] * mixw[k*32 + o],  k = o_in*2+g
    float mix = 0.f;
#pragma unroll
    for (int k = 0; k < 64; ++k)
        mix = fmaf(smXn[warp][k], smMix[k * 32 + lane], mix);

    // self interaction: out_o += b[o] + sum_f x[f] * selfw[o,f]
    float x = in_feat[(size_t)a * 32 + lane];
    float sp_acc = smB[lane];
#pragma unroll
    for (int f = 0; f < 32; ++f) {
        float xf = __shfl_sync(0xffffffffu, x, f);
        sp_acc = fmaf(xf, smSelfT[f * 32 + lane], sp_acc);
    }

    out[(size_t)a * 32 + lane] = mix + sp_acc;
}

// ---------------------------------------------------------------------------
extern "C" void kernel_launch(void* const* d_in, const int* in_sizes, int n_in,
                              void* d_out, int out_size)
{
    const float* in_feat = (const float*)d_in[0];
    const float* rhat    = (const float*)d_in[1];
    const float* dist    = (const float*)d_in[2];
    const float* intw    = (const float*)d_in[3];
    const float* selfw   = (const float*)d_in[4];
    const float* selfb   = (const float*)d_in[5];
    const float* mixw    = (const float*)d_in[6];
    const float* gnw     = (const float*)d_in[7];
    const float* gnb     = (const float*)d_in[8];
    const float* mu      = (const float*)d_in[9];
    const float* sigma   = (const float*)d_in[10];
    const int*   pf      = (const int*)d_in[11];
    const int*   ps      = (const int*)d_in[12];
    float* out = (float*)d_out;

    proj_kernel<<<N_ATOMS / 32, PROJ_THREADS>>>(in_feat, intw);
    {
        int total = N_PAIRS * N_DIST;
        sense_kernel<<<(total + 255) / 256, 256>>>(dist, mu, sigma);
    }
    {
        int blocks = (N_ATOMS + WPB - 1) / WPB;
        main_kernel<<<blocks, WPB * 32>>>(rhat, pf, ps, in_feat,
                                          selfw, selfb, mixw, gnw, gnb, out);
    }
}

// round 6
// speedup vs baseline: 2.5024x; 1.1747x over previous
#include <cuda_runtime.h>
#include <cstdint>

// Problem constants (fixed by the dataset)
#define N_ATOMS  8000
#define N_PAIRS  80000
#define NF_IN    32
#define NF_OUT   32
#define N_DIST   16
#define N_COMP   4
#define N_INV    2
#define HARD_CUTOFF 6.5f
#define GN_EPS   1e-5f

// Scratch (static device arrays — no allocation)
// g_proj layout: (j, o, d)  -> g_proj[j*512 + o*16 + d]
__device__ float g_proj[N_ATOMS * N_DIST * NF_OUT];   // 16.4 MB
__device__ float g_h[N_PAIRS * NF_OUT];               // (p, o) : 10.2 MB

// ---------------------------------------------------------------------------
// K1: g[j,o,d] = sum_f feat[j,f] * W[d,o,f]
// Warp handles 4 atoms; lane = o; 16 d-accumulators per atom.
// 128 threads/block (4 warps, 16 atoms) for better occupancy spread.
// ---------------------------------------------------------------------------
#define PROJ_THREADS 128   // 4 warps -> 16 atoms/block -> 500 blocks

__global__ void __launch_bounds__(PROJ_THREADS) proj_kernel(
    const float* __restrict__ feat, const float* __restrict__ W)
{
    __shared__ float smW[16 * 512];   // 32 KB: [fh][d*32+o]
    int tid  = threadIdx.x;
    int warp = tid >> 5, lane = tid & 31;
    int atom0 = blockIdx.x * 16 + warp * 4;

    // lane holds feat[j][lane] for each of its 4 atoms
    float x0 = feat[(size_t)(atom0 + 0) * 32 + lane];
    float x1 = feat[(size_t)(atom0 + 1) * 32 + lane];
    float x2 = feat[(size_t)(atom0 + 2) * 32 + lane];
    float x3 = feat[(size_t)(atom0 + 3) * 32 + lane];

    float acc0[16], acc1[16], acc2[16], acc3[16];
#pragma unroll
    for (int d = 0; d < 16; ++d) { acc0[d] = acc1[d] = acc2[d] = acc3[d] = 0.f; }

    for (int half = 0; half < 2; ++half) {
        __syncthreads();
        // Load W half-tile: smW[fh*512 + s] = W[s*32 + half*16 + fh], s = d*32+o
        for (int i = tid; i < 2048; i += PROJ_THREADS) {
            int s   = i >> 2;
            int fh4 = (i & 3) * 4;
            float4 w = *(const float4*)(W + (size_t)s * 32 + half * 16 + fh4);
            smW[(fh4 + 0) * 512 + s] = w.x;
            smW[(fh4 + 1) * 512 + s] = w.y;
            smW[(fh4 + 2) * 512 + s] = w.z;
            smW[(fh4 + 3) * 512 + s] = w.w;
        }
        __syncthreads();
#pragma unroll
        for (int fh = 0; fh < 16; ++fh) {
            int f = half * 16 + fh;
            float xf0 = __shfl_sync(0xffffffffu, x0, f);
            float xf1 = __shfl_sync(0xffffffffu, x1, f);
            float xf2 = __shfl_sync(0xffffffffu, x2, f);
            float xf3 = __shfl_sync(0xffffffffu, x3, f);
            const float* wrow = smW + fh * 512 + lane;
#pragma unroll
            for (int d = 0; d < 16; ++d) {
                float w = wrow[d * 32];          // conflict-free LDS
                acc0[d] = fmaf(xf0, w, acc0[d]);
                acc1[d] = fmaf(xf1, w, acc1[d]);
                acc2[d] = fmaf(xf2, w, acc2[d]);
                acc3[d] = fmaf(xf3, w, acc3[d]);
            }
        }
    }

    // Store g[j][o][d]: per-lane 16 consecutive floats -> 4x STG.128
    float4* o0 = (float4*)(g_proj + (size_t)(atom0 + 0) * 512 + lane * 16);
    float4* o1 = (float4*)(g_proj + (size_t)(atom0 + 1) * 512 + lane * 16);
    float4* o2 = (float4*)(g_proj + (size_t)(atom0 + 2) * 512 + lane * 16);
    float4* o3 = (float4*)(g_proj + (size_t)(atom0 + 3) * 512 + lane * 16);
#pragma unroll
    for (int q = 0; q < 4; ++q) {
        o0[q] = make_float4(acc0[q*4], acc0[q*4+1], acc0[q*4+2], acc0[q*4+3]);
        o1[q] = make_float4(acc1[q*4], acc1[q*4+1], acc1[q*4+2], acc1[q*4+3]);
        o2[q] = make_float4(acc2[q*4], acc2[q*4+1], acc2[q*4+2], acc2[q*4+3]);
        o3[q] = make_float4(acc3[q*4], acc3[q*4+1], acc3[q*4+2], acc3[q*4+3]);
    }
}

// ---------------------------------------------------------------------------
// K2 (pair kernel): warp per pair, lane = o.
//   sense[p,d] computed inline (lane d = lane&15 computes, shfl-broadcast)
//   h[p,o] = sum_d sense[p,d] * g[j,o,d]
// ---------------------------------------------------------------------------
#define PAIR_THREADS 256   // 8 pairs per block

__global__ void __launch_bounds__(PAIR_THREADS) pair_kernel(
    const float* __restrict__ dist,
    const float* __restrict__ mu,
    const float* __restrict__ sigma,
    const int*   __restrict__ pair_second)
{
    int warp = threadIdx.x >> 5, lane = threadIdx.x & 31;
    int p = blockIdx.x * 8 + warp;
    if (p >= N_PAIRS) return;

    int j = pair_second[p];                      // broadcast
    float dd = dist[p];                          // broadcast

    // lane computes sense for d = lane & 15 (duplicated across halves)
    int d = lane & 15;
    float invd = 1.0f / dd;
    float t = (invd - mu[d]) / sigma[d];
    float sval = expf(-0.5f * t * t);
    float cut = 0.f;
    if (dd < HARD_CUTOFF) {
        float c = cosf(0.5f * 3.14159265358979323846f * dd / HARD_CUTOFF);
        cut = c * c;
    }
    sval *= cut;

    // load g[j][lane][0..15] : 4 independent LDG.128
    const float4* gp = (const float4*)(g_proj + (size_t)j * 512 + lane * 16);
    float4 g0 = gp[0], g1 = gp[1], g2 = gp[2], g3 = gp[3];

    float h;
    h = g0.x * __shfl_sync(0xffffffffu, sval, 0);
    h = fmaf(g0.y, __shfl_sync(0xffffffffu, sval, 1), h);
    h = fmaf(g0.z, __shfl_sync(0xffffffffu, sval, 2), h);
    h = fmaf(g0.w, __shfl_sync(0xffffffffu, sval, 3), h);
    h = fmaf(g1.x, __shfl_sync(0xffffffffu, sval, 4), h);
    h = fmaf(g1.y, __shfl_sync(0xffffffffu, sval, 5), h);
    h = fmaf(g1.z, __shfl_sync(0xffffffffu, sval, 6), h);
    h = fmaf(g1.w, __shfl_sync(0xffffffffu, sval, 7), h);
    h = fmaf(g2.x, __shfl_sync(0xffffffffu, sval, 8), h);
    h = fmaf(g2.y, __shfl_sync(0xffffffffu, sval, 9), h);
    h = fmaf(g2.z, __shfl_sync(0xffffffffu, sval, 10), h);
    h = fmaf(g2.w, __shfl_sync(0xffffffffu, sval, 11), h);
    h = fmaf(g3.x, __shfl_sync(0xffffffffu, sval, 12), h);
    h = fmaf(g3.y, __shfl_sync(0xffffffffu, sval, 13), h);
    h = fmaf(g3.z, __shfl_sync(0xffffffffu, sval, 14), h);
    h = fmaf(g3.w, __shfl_sync(0xffffffffu, sval, 15), h);

    g_h[(size_t)p * 32 + lane] = h;
}

// ---------------------------------------------------------------------------
// K3 (atom kernel): one warp per atom (lane = o).
//   Segment-sum of rhat[p,c] * h[p,o]  -> invariants -> GN -> mix -> +self
// ---------------------------------------------------------------------------
#define WPB 8  // warps per block

__device__ __forceinline__ float warp_sum(float v) {
#pragma unroll
    for (int s = 16; s; s >>= 1) v += __shfl_xor_sync(0xffffffffu, v, s);
    return v;
}

__global__ void __launch_bounds__(WPB * 32) atom_kernel(
    const float* __restrict__ rhat,         // (P, 4)
    const int*   __restrict__ pair_first,   // (P,) sorted
    const float* __restrict__ in_feat,      // (N, 32)
    const float* __restrict__ selfw,        // (32, 32) [o, f]
    const float* __restrict__ selfb,        // (32,)
    const float* __restrict__ mixw,         // (32, 2, 32) flat 2048
    const float* __restrict__ gnw,          // (64,)
    const float* __restrict__ gnb,          // (64,)
    float*       __restrict__ out)          // (N, 32)
{
    __shared__ float smMix[2048];           // [ (o_in*2+g)*32 + o_out ]
    __shared__ float smSelfT[1024];         // transposed: [f*32 + o]
    __shared__ float smB[32], smGnW[64], smGnB[64];
    __shared__ float smXn[WPB][64];

    int tid = threadIdx.x;
    for (int i = tid; i < 2048; i += blockDim.x) smMix[i] = mixw[i];
    for (int i = tid; i < 1024; i += blockDim.x) {
        int o = i >> 5, f = i & 31;
        smSelfT[f * 32 + o] = selfw[i];
    }
    if (tid < 32) smB[tid] = selfb[tid];
    if (tid < 64) { smGnW[tid] = gnw[tid]; smGnB[tid] = gnb[tid]; }
    __syncthreads();

    int warp = tid >> 5, lane = tid & 31;
    int a = blockIdx.x * WPB + warp;
    if (a >= N_ATOMS) return;

    // segment [lo, hi) of this atom's pairs via binary search (lane 0)
    int lo = 0, hi = 0;
    if (lane == 0) {
        int l = 0, r = N_PAIRS;
        while (l < r) { int m = (l + r) >> 1; if (pair_first[m] < a) l = m + 1; else r = m; }
        lo = l;
        r = N_PAIRS;
        while (l < r) { int m = (l + r) >> 1; if (pair_first[m] < a + 1) l = m + 1; else r = m; }
        hi = l;
    }
    lo = __shfl_sync(0xffffffffu, lo, 0);
    hi = __shfl_sync(0xffffffffu, hi, 0);

    float acc0 = 0.f, acc1 = 0.f, acc2 = 0.f, acc3 = 0.f;
    int p = lo;
    // unroll x4 for MLP
    for (; p + 3 < hi; p += 4) {
        float h0 = g_h[(size_t)(p + 0) * 32 + lane];
        float h1 = g_h[(size_t)(p + 1) * 32 + lane];
        float h2 = g_h[(size_t)(p + 2) * 32 + lane];
        float h3 = g_h[(size_t)(p + 3) * 32 + lane];
        float4 r0 = *(const float4*)(rhat + (size_t)(p + 0) * 4);
        float4 r1 = *(const float4*)(rhat + (size_t)(p + 1) * 4);
        float4 r2 = *(const float4*)(rhat + (size_t)(p + 2) * 4);
        float4 r3 = *(const float4*)(rhat + (size_t)(p + 3) * 4);
        acc0 = fmaf(r0.x, h0, acc0); acc1 = fmaf(r0.y, h0, acc1);
        acc2 = fmaf(r0.z, h0, acc2); acc3 = fmaf(r0.w, h0, acc3);
        acc0 = fmaf(r1.x, h1, acc0); acc1 = fmaf(r1.y, h1, acc1);
        acc2 = fmaf(r1.z, h1, acc2); acc3 = fmaf(r1.w, h1, acc3);
        acc0 = fmaf(r2.x, h2, acc0); acc1 = fmaf(r2.y, h2, acc1);
        acc2 = fmaf(r2.z, h2, acc2); acc3 = fmaf(r2.w, h2, acc3);
        acc0 = fmaf(r3.x, h3, acc0); acc1 = fmaf(r3.y, h3, acc1);
        acc2 = fmaf(r3.z, h3, acc2); acc3 = fmaf(r3.w, h3, acc3);
    }
    for (; p < hi; ++p) {
        float h = g_h[(size_t)p * 32 + lane];
        float4 r = *(const float4*)(rhat + (size_t)p * 4);
        acc0 = fmaf(r.x, h, acc0);
        acc1 = fmaf(r.y, h, acc1);
        acc2 = fmaf(r.z, h, acc2);
        acc3 = fmaf(r.w, h, acc3);
    }

    // invariants: l=0 scalar, |l=1|^2
    float inv0 = acc0;
    float inv1 = acc1 * acc1 + acc2 * acc2 + acc3 * acc3;

    // GroupNorm per group (channel dim = 32 lanes), biased var
    float m0 = warp_sum(inv0) * (1.f / 32.f);
    float q0 = warp_sum(inv0 * inv0) * (1.f / 32.f);
    float xn0 = (inv0 - m0) * rsqrtf(q0 - m0 * m0 + GN_EPS) * smGnW[lane] + smGnB[lane];
    float m1 = warp_sum(inv1) * (1.f / 32.f);
    float q1 = warp_sum(inv1 * inv1) * (1.f / 32.f);
    float xn1 = (inv1 - m1) * rsqrtf(q1 - m1 * m1 + GN_EPS) * smGnW[32 + lane] + smGnB[32 + lane];

    // stage normalized invariants: norm_inv layout index o*2+g
    smXn[warp][lane * 2 + 0] = xn0;
    smXn[warp][lane * 2 + 1] = xn1;
    __syncwarp();

    // mixing: out_o = sum_k smXn[k] * mixw[k*32 + o],  k = o_in*2+g
    float mix = 0.f;
#pragma unroll
    for (int k = 0; k < 64; ++k)
        mix = fmaf(smXn[warp][k], smMix[k * 32 + lane], mix);

    // self interaction: out_o += b[o] + sum_f x[f] * selfw[o,f]
    float x = in_feat[(size_t)a * 32 + lane];
    float sp_acc = smB[lane];
#pragma unroll
    for (int f = 0; f < 32; ++f) {
        float xf = __shfl_sync(0xffffffffu, x, f);
        sp_acc = fmaf(xf, smSelfT[f * 32 + lane], sp_acc);
    }

    out[(size_t)a * 32 + lane] = mix + sp_acc;
}

// ---------------------------------------------------------------------------
extern "C" void kernel_launch(void* const* d_in, const int* in_sizes, int n_in,
                              void* d_out, int out_size)
{
    const float* in_feat = (const float*)d_in[0];
    const float* rhat    = (const float*)d_in[1];
    const float* dist    = (const float*)d_in[2];
    const float* intw    = (const float*)d_in[3];
    const float* selfw   = (const float*)d_in[4];
    const float* selfb   = (const float*)d_in[5];
    const float* mixw    = (const float*)d_in[6];
    const float* gnw     = (const float*)d_in[7];
    const float* gnb     = (const float*)d_in[8];
    const float* mu      = (const float*)d_in[9];
    const float* sigma   = (const float*)d_in[10];
    const int*   pf      = (const int*)d_in[11];
    const int*   ps      = (const int*)d_in[12];
    float* out = (float*)d_out;

    proj_kernel<<<N_ATOMS / 16, PROJ_THREADS>>>(in_feat, intw);
    pair_kernel<<<(N_PAIRS + 7) / 8, PAIR_THREADS>>>(dist, mu, sigma, ps);
    {
        int blocks = (N_ATOMS + WPB - 1) / WPB;
        atom_kernel<<<blocks, WPB * 32>>>(rhat, pf, in_feat,
                                          selfw, selfb, mixw, gnw, gnb, out);
    }
}

// round 7
// speedup vs baseline: 2.5367x; 1.0137x over previous
#include <cuda_runtime.h>
#include <cstdint>

// Problem constants (fixed by the dataset)
#define N_ATOMS  8000
#define N_PAIRS  80000
#define NF_IN    32
#define NF_OUT   32
#define N_DIST   16
#define N_COMP   4
#define N_INV    2
#define HARD_CUTOFF 6.5f
#define GN_EPS   1e-5f

// Scratch (static device arrays — no allocation)
// g_proj layout: (j, o, d)  -> g_proj[j*512 + o*16 + d]
__device__ float g_proj[N_ATOMS * N_DIST * NF_OUT];   // 16.4 MB
__device__ float g_h[N_PAIRS * NF_OUT];               // (p, o) : 10.2 MB

// ---------------------------------------------------------------------------
// K1: g[j,o,d] = sum_f feat[j,f] * W[d,o,f]
// 256 threads = 8 warps. Warp pair (2w, 2w+1) covers 4 atoms;
// even warp: d 0-7, odd warp: d 8-15  ->  32 accumulator regs per thread.
// W staged in smem in two 16-f half-tiles: smW[fh*513 + d*32 + o].
// ---------------------------------------------------------------------------
#define PROJ_THREADS 256
#define SMW_STRIDE 513

__global__ void __launch_bounds__(PROJ_THREADS) proj_kernel(
    const float* __restrict__ feat, const float* __restrict__ W)
{
    __shared__ float smW[16 * SMW_STRIDE];   // ~32.1 KB
    int tid  = threadIdx.x;
    int warp = tid >> 5, lane = tid & 31;
    int grp    = warp >> 1;          // 0..3 : atom group
    int dhalf  = (warp & 1) * 8;     // 0 or 8
    int atom0  = blockIdx.x * 16 + grp * 4;

    // lane holds feat[j][lane] for each of its 4 atoms
    float x0 = feat[(size_t)(atom0 + 0) * 32 + lane];
    float x1 = feat[(size_t)(atom0 + 1) * 32 + lane];
    float x2 = feat[(size_t)(atom0 + 2) * 32 + lane];
    float x3 = feat[(size_t)(atom0 + 3) * 32 + lane];

    float acc0[8], acc1[8], acc2[8], acc3[8];
#pragma unroll
    for (int d = 0; d < 8; ++d) { acc0[d] = acc1[d] = acc2[d] = acc3[d] = 0.f; }

    for (int half = 0; half < 2; ++half) {
        __syncthreads();
        // smW[fh*513 + s] = W[s*32 + half*16 + fh],  s = d*32 + o
        for (int i = tid; i < 2048; i += PROJ_THREADS) {
            int s   = i >> 2;
            int fh4 = (i & 3) * 4;
            float4 w = *(const float4*)(W + (size_t)s * 32 + half * 16 + fh4);
            smW[(fh4 + 0) * SMW_STRIDE + s] = w.x;
            smW[(fh4 + 1) * SMW_STRIDE + s] = w.y;
            smW[(fh4 + 2) * SMW_STRIDE + s] = w.z;
            smW[(fh4 + 3) * SMW_STRIDE + s] = w.w;
        }
        __syncthreads();
#pragma unroll
        for (int fh = 0; fh < 16; ++fh) {
            int f = half * 16 + fh;
            float xf0 = __shfl_sync(0xffffffffu, x0, f);
            float xf1 = __shfl_sync(0xffffffffu, x1, f);
            float xf2 = __shfl_sync(0xffffffffu, x2, f);
            float xf3 = __shfl_sync(0xffffffffu, x3, f);
            const float* wrow = smW + fh * SMW_STRIDE + dhalf * 32 + lane;
#pragma unroll
            for (int d = 0; d < 8; ++d) {
                float w = wrow[d * 32];          // conflict-free LDS
                acc0[d] = fmaf(xf0, w, acc0[d]);
                acc1[d] = fmaf(xf1, w, acc1[d]);
                acc2[d] = fmaf(xf2, w, acc2[d]);
                acc3[d] = fmaf(xf3, w, acc3[d]);
            }
        }
    }

    // Store g[j][o][dhalf..dhalf+7]: 2x STG.128 per atom per lane
    float4* o0 = (float4*)(g_proj + (size_t)(atom0 + 0) * 512 + lane * 16 + dhalf);
    float4* o1 = (float4*)(g_proj + (size_t)(atom0 + 1) * 512 + lane * 16 + dhalf);
    float4* o2 = (float4*)(g_proj + (size_t)(atom0 + 2) * 512 + lane * 16 + dhalf);
    float4* o3 = (float4*)(g_proj + (size_t)(atom0 + 3) * 512 + lane * 16 + dhalf);
#pragma unroll
    for (int q = 0; q < 2; ++q) {
        o0[q] = make_float4(acc0[q*4], acc0[q*4+1], acc0[q*4+2], acc0[q*4+3]);
        o1[q] = make_float4(acc1[q*4], acc1[q*4+1], acc1[q*4+2], acc1[q*4+3]);
        o2[q] = make_float4(acc2[q*4], acc2[q*4+1], acc2[q*4+2], acc2[q*4+3]);
        o3[q] = make_float4(acc3[q*4], acc3[q*4+1], acc3[q*4+2], acc3[q*4+3]);
    }
}

// ---------------------------------------------------------------------------
// K2 (pair kernel): warp per pair, lane = o.
//   sense[p,d] computed inline (lane d = lane&15 computes, shfl-broadcast)
//   h[p,o] = sum_d sense[p,d] * g[j,o,d]
// ---------------------------------------------------------------------------
#define PAIR_THREADS 256   // 8 pairs per block

__global__ void __launch_bounds__(PAIR_THREADS) pair_kernel(
    const float* __restrict__ dist,
    const float* __restrict__ mu,
    const float* __restrict__ sigma,
    const int*   __restrict__ pair_second)
{
    int warp = threadIdx.x >> 5, lane = threadIdx.x & 31;
    int p = blockIdx.x * 8 + warp;
    if (p >= N_PAIRS) return;

    int j = pair_second[p];                      // broadcast
    float dd = dist[p];                          // broadcast

    // lane computes sense for d = lane & 15 (duplicated across halves)
    int d = lane & 15;
    float invd = 1.0f / dd;
    float t = (invd - mu[d]) / sigma[d];
    float sval = __expf(-0.5f * t * t);
    float cut = 0.f;
    if (dd < HARD_CUTOFF) {
        float c = __cosf(0.5f * 3.14159265358979323846f * dd / HARD_CUTOFF);
        cut = c * c;
    }
    sval *= cut;

    // load g[j][lane][0..15] : 4 independent LDG.128
    const float4* gp = (const float4*)(g_proj + (size_t)j * 512 + lane * 16);
    float4 g0 = gp[0], g1 = gp[1], g2 = gp[2], g3 = gp[3];

    float h;
    h = g0.x * __shfl_sync(0xffffffffu, sval, 0);
    h = fmaf(g0.y, __shfl_sync(0xffffffffu, sval, 1), h);
    h = fmaf(g0.z, __shfl_sync(0xffffffffu, sval, 2), h);
    h = fmaf(g0.w, __shfl_sync(0xffffffffu, sval, 3), h);
    h = fmaf(g1.x, __shfl_sync(0xffffffffu, sval, 4), h);
    h = fmaf(g1.y, __shfl_sync(0xffffffffu, sval, 5), h);
    h = fmaf(g1.z, __shfl_sync(0xffffffffu, sval, 6), h);
    h = fmaf(g1.w, __shfl_sync(0xffffffffu, sval, 7), h);
    h = fmaf(g2.x, __shfl_sync(0xffffffffu, sval, 8), h);
    h = fmaf(g2.y, __shfl_sync(0xffffffffu, sval, 9), h);
    h = fmaf(g2.z, __shfl_sync(0xffffffffu, sval, 10), h);
    h = fmaf(g2.w, __shfl_sync(0xffffffffu, sval, 11), h);
    h = fmaf(g3.x, __shfl_sync(0xffffffffu, sval, 12), h);
    h = fmaf(g3.y, __shfl_sync(0xffffffffu, sval, 13), h);
    h = fmaf(g3.z, __shfl_sync(0xffffffffu, sval, 14), h);
    h = fmaf(g3.w, __shfl_sync(0xffffffffu, sval, 15), h);

    g_h[(size_t)p * 32 + lane] = h;
}

// ---------------------------------------------------------------------------
// K3 (atom kernel): one warp per atom (lane = o).
//   Segment-sum of rhat[p,c] * h[p,o]  -> invariants -> GN -> mix -> +self
// ---------------------------------------------------------------------------
#define WPB 8  // warps per block

__device__ __forceinline__ float warp_sum(float v) {
#pragma unroll
    for (int s = 16; s; s >>= 1) v += __shfl_xor_sync(0xffffffffu, v, s);
    return v;
}

__global__ void __launch_bounds__(WPB * 32) atom_kernel(
    const float* __restrict__ rhat,         // (P, 4)
    const int*   __restrict__ pair_first,   // (P,) sorted
    const float* __restrict__ in_feat,      // (N, 32)
    const float* __restrict__ selfw,        // (32, 32) [o, f]
    const float* __restrict__ selfb,        // (32,)
    const float* __restrict__ mixw,         // (32, 2, 32) flat 2048
    const float* __restrict__ gnw,          // (64,)
    const float* __restrict__ gnb,          // (64,)
    float*       __restrict__ out)          // (N, 32)
{
    __shared__ float smMix[2048];           // [ (o_in*2+g)*32 + o_out ]
    __shared__ float smSelfT[1024];         // transposed: [f*32 + o]
    __shared__ float smB[32], smGnW[64], smGnB[64];
    __shared__ float smXn[WPB][64];

    int tid = threadIdx.x;
    for (int i = tid; i < 2048; i += blockDim.x) smMix[i] = mixw[i];
    for (int i = tid; i < 1024; i += blockDim.x) {
        int o = i >> 5, f = i & 31;
        smSelfT[f * 32 + o] = selfw[i];
    }
    if (tid < 32) smB[tid] = selfb[tid];
    if (tid < 64) { smGnW[tid] = gnw[tid]; smGnB[tid] = gnb[tid]; }
    __syncthreads();

    int warp = tid >> 5, lane = tid & 31;
    int a = blockIdx.x * WPB + warp;
    if (a >= N_ATOMS) return;

    // segment [lo, hi) of this atom's pairs via binary search (lane 0)
    int lo = 0, hi = 0;
    if (lane == 0) {
        int l = 0, r = N_PAIRS;
        while (l < r) { int m = (l + r) >> 1; if (pair_first[m] < a) l = m + 1; else r = m; }
        lo = l;
        r = N_PAIRS;
        while (l < r) { int m = (l + r) >> 1; if (pair_first[m] < a + 1) l = m + 1; else r = m; }
        hi = l;
    }
    lo = __shfl_sync(0xffffffffu, lo, 0);
    hi = __shfl_sync(0xffffffffu, hi, 0);

    float acc0 = 0.f, acc1 = 0.f, acc2 = 0.f, acc3 = 0.f;
    int p = lo;
    // unroll x4 for MLP
    for (; p + 3 < hi; p += 4) {
        float h0 = g_h[(size_t)(p + 0) * 32 + lane];
        float h1 = g_h[(size_t)(p + 1) * 32 + lane];
        float h2 = g_h[(size_t)(p + 2) * 32 + lane];
        float h3 = g_h[(size_t)(p + 3) * 32 + lane];
        float4 r0 = *(const float4*)(rhat + (size_t)(p + 0) * 4);
        float4 r1 = *(const float4*)(rhat + (size_t)(p + 1) * 4);
        float4 r2 = *(const float4*)(rhat + (size_t)(p + 2) * 4);
        float4 r3 = *(const float4*)(rhat + (size_t)(p + 3) * 4);
        acc0 = fmaf(r0.x, h0, acc0); acc1 = fmaf(r0.y, h0, acc1);
        acc2 = fmaf(r0.z, h0, acc2); acc3 = fmaf(r0.w, h0, acc3);
        acc0 = fmaf(r1.x, h1, acc0); acc1 = fmaf(r1.y, h1, acc1);
        acc2 = fmaf(r1.z, h1, acc2); acc3 = fmaf(r1.w, h1, acc3);
        acc0 = fmaf(r2.x, h2, acc0); acc1 = fmaf(r2.y, h2, acc1);
        acc2 = fmaf(r2.z, h2, acc2); acc3 = fmaf(r2.w, h2, acc3);
        acc0 = fmaf(r3.x, h3, acc0); acc1 = fmaf(r3.y, h3, acc1);
        acc2 = fmaf(r3.z, h3, acc2); acc3 = fmaf(r3.w, h3, acc3);
    }
    for (; p < hi; ++p) {
        float h = g_h[(size_t)p * 32 + lane];
        float4 r = *(const float4*)(rhat + (size_t)p * 4);
        acc0 = fmaf(r.x, h, acc0);
        acc1 = fmaf(r.y, h, acc1);
        acc2 = fmaf(r.z, h, acc2);
        acc3 = fmaf(r.w, h, acc3);
    }

    // invariants: l=0 scalar, |l=1|^2
    float inv0 = acc0;
    float inv1 = acc1 * acc1 + acc2 * acc2 + acc3 * acc3;

    // GroupNorm per group (channel dim = 32 lanes), biased var
    float m0 = warp_sum(inv0) * (1.f / 32.f);
    float q0 = warp_sum(inv0 * inv0) * (1.f / 32.f);
    float xn0 = (inv0 - m0) * rsqrtf(q0 - m0 * m0 + GN_EPS) * smGnW[lane] + smGnB[lane];
    float m1 = warp_sum(inv1) * (1.f / 32.f);
    float q1 = warp_sum(inv1 * inv1) * (1.f / 32.f);
    float xn1 = (inv1 - m1) * rsqrtf(q1 - m1 * m1 + GN_EPS) * smGnW[32 + lane] + smGnB[32 + lane];

    // stage normalized invariants: norm_inv layout index o*2+g
    smXn[warp][lane * 2 + 0] = xn0;
    smXn[warp][lane * 2 + 1] = xn1;
    __syncwarp();

    // mixing: out_o = sum_k smXn[k] * mixw[k*32 + o],  k = o_in*2+g
    float mix = 0.f;
#pragma unroll
    for (int k = 0; k < 64; ++k)
        mix = fmaf(smXn[warp][k], smMix[k * 32 + lane], mix);

    // self interaction: out_o += b[o] + sum_f x[f] * selfw[o,f]
    float x = in_feat[(size_t)a * 32 + lane];
    float sp_acc = smB[lane];
#pragma unroll
    for (int f = 0; f < 32; ++f) {
        float xf = __shfl_sync(0xffffffffu, x, f);
        sp_acc = fmaf(xf, smSelfT[f * 32 + lane], sp_acc);
    }

    out[(size_t)a * 32 + lane] = mix + sp_acc;
}

// ---------------------------------------------------------------------------
extern "C" void kernel_launch(void* const* d_in, const int* in_sizes, int n_in,
                              void* d_out, int out_size)
{
    const float* in_feat = (const float*)d_in[0];
    const float* rhat    = (const float*)d_in[1];
    const float* dist    = (const float*)d_in[2];
    const float* intw    = (const float*)d_in[3];
    const float* selfw   = (const float*)d_in[4];
    const float* selfb   = (const float*)d_in[5];
    const float* mixw    = (const float*)d_in[6];
    const float* gnw     = (const float*)d_in[7];
    const float* gnb     = (const float*)d_in[8];
    const float* mu      = (const float*)d_in[9];
    const float* sigma   = (const float*)d_in[10];
    const int*   pf      = (const int*)d_in[11];
    const int*   ps      = (const int*)d_in[12];
    float* out = (float*)d_out;

    proj_kernel<<<N_ATOMS / 16, PROJ_THREADS>>>(in_feat, intw);
    pair_kernel<<<(N_PAIRS + 7) / 8, PAIR_THREADS>>>(dist, mu, sigma, ps);
    {
        int blocks = (N_ATOMS + WPB - 1) / WPB;
        atom_kernel<<<blocks, WPB * 32>>>(rhat, pf, in_feat,
                                          selfw, selfb, mixw, gnw, gnb, out);
    }
}